// round 14
// baseline (speedup 1.0000x reference)
#include <cuda_runtime.h>

// ----------------------------------------------------------------------------
// Despawn2D: 6-level 2D db4 circular DWT + sigmoid threshold + inverse DWT.
// fwd0, fwd1: fused tiled kernels (R8-proven; fwd0 block(0,0) resets g_bar).
// mega: blocks [0,ND) run lev2..5 fwd + 5..2 bwd tail (grid barriers);
//       blocks [ND,512) precompute H0/H1 = colrecon(hh,hl) for levels 0/1.
// bwd1, bwd0: combine kernels (H + colrecon(lh,approx) -> row recon),
//             with split scalar smem arrays (no stride-8 half-wavefronts).
// d_out layout: [ recon (4096*4096) | flat coeffs (4096*4096) ]
// flat per level: (s2, 3*s2) row-major hh|hl|lh, then approx (64*64) last.
// ----------------------------------------------------------------------------

#define NSIDE 4096
#define NB_MEGA 512
#define ND 256

__device__ float g_bufA[2048u * 2048u];
__device__ float g_bufB[2048u * 2048u];
__device__ float g_H[4096u * 2048u + 2048u * 1024u];   // H0 (32MB) + H1 (8MB)
__device__ unsigned g_bar;

__device__ __forceinline__ float2 fma2(float2 a, float2 b, float2 c)
{
    float2 d;
    asm("fma.rn.f32x2 %0, %1, %2, %3;"
        : "=l"(reinterpret_cast<unsigned long long&>(d))
        : "l"(reinterpret_cast<unsigned long long&>(a)),
          "l"(reinterpret_cast<unsigned long long&>(b)),
          "l"(reinterpret_cast<unsigned long long&>(c)));
    return d;
}

__device__ __forceinline__ float thrf(float t, float a, float bp, float bm)
{
    float s1 = 1.0f / (1.0f + __expf(-a * (t - bp)));
    float s2 = 1.0f / (1.0f + __expf( a * (t + bm)));
    return t * (s1 + s2);
}

__device__ __forceinline__ void grid_barrier(unsigned* cnt, unsigned target)
{
    __syncthreads();
    if (threadIdx.x == 0) {
        __threadfence();
        atomicAdd(cnt, 1u);
        while (*((volatile unsigned*)cnt) < target) { __nanosleep(64); }
        __threadfence();
    }
    __syncthreads();
}

struct Filt {
    float hH[8], wH[8], hV[8], wV[8];
    float2 hH2[8], wH2[8], hV2[8], wV2[8];
    float2 cxe[4], cxo[4];
    float2 cve[4], cvo[4];
};

__device__ __forceinline__ void filt_load(Filt& F, const float* hHp, const float* hVp, int tid)
{
    if (tid < 8) { F.hH[tid] = hHp[tid]; F.hV[tid] = hVp[tid]; }
    __syncthreads();
    if (tid < 8) {
        float s = (tid & 1) ? -1.0f : 1.0f;
        float wh = F.hH[7 - tid] * s;
        float wv = F.hV[7 - tid] * s;
        F.wH[tid] = wh;           F.wV[tid] = wv;
        F.hH2[tid] = make_float2(F.hH[tid], F.hH[tid]);
        F.wH2[tid] = make_float2(wh, wh);
        F.hV2[tid] = make_float2(F.hV[tid], F.hV[tid]);
        F.wV2[tid] = make_float2(wv, wv);
    }
    __syncthreads();
    if (tid < 4) {
        F.cxe[tid] = make_float2(F.wH[2 * tid],     F.hH[2 * tid]);
        F.cxo[tid] = make_float2(F.wH[2 * tid + 1], F.hH[2 * tid + 1]);
        F.cve[tid] = make_float2(F.wV[2 * tid],     F.hV[2 * tid]);
        F.cvo[tid] = make_float2(F.wV[2 * tid + 1], F.hV[2 * tid + 1]);
    }
    __syncthreads();
}

// ----------------------------------------------------------------------------
// Big fused forward (TI=32). R8-proven scalar high-MLP loads.
// Block (0,0) resets g_bar (graph-safe: stream-ordered before mega).
// ----------------------------------------------------------------------------
__global__ __launch_bounds__(256)
void fwd2d32(const float* __restrict__ X, int s, long ldx,
             float* __restrict__ flatb,
             float* __restrict__ LL, long ldll, int thrLL,
             const float* __restrict__ hHp, const float* __restrict__ hVp,
             const float* __restrict__ pA, const float* __restrict__ pBp,
             const float* __restrict__ pBm)
{
    __shared__ __align__(16) float4 sx4[70][19];
    __shared__ __align__(16) float2 sda[70][34];
    __shared__ Filt F;
    const int tid = threadIdx.x;
    const int wid = tid >> 5, lane = tid & 31;
    if (tid == 0 && blockIdx.x == 0 && blockIdx.y == 0) g_bar = 0;
    filt_load(F, hHp, hVp, tid);

    const int s2 = s >> 1;
    const int i0 = blockIdx.y << 5, j0 = blockIdx.x << 5;
    const int mask = s - 1;
    const int rb = 2 * i0 - 7, cb = 2 * j0 - 7;

#pragma unroll
    for (int k = 0; k < 9; k++) {
        const int rr = wid + 8 * k;
        if (rr < 70) {
            const float* xr = X + (long)((rb + rr) & mask) * ldx;
            float* dst = (float*)(&sx4[rr][0]);
#pragma unroll
            for (int cc = 0; cc < 3; cc++) {
                const int c = lane + 32 * cc;
                if (c < 70) dst[c] = xr[(cb + c) & mask];
            }
        }
    }
    __syncthreads();

#pragma unroll
    for (int k = 0; k < 5; k++) {
        const int t = tid + 256 * k;
        if (t < 70 * 16) {
            const int rr = t >> 4, jp = t & 15;
            float4 q0 = sx4[rr][jp], q1 = sx4[rr][jp + 1], q2 = sx4[rr][jp + 2];
            float xx[12] = {q0.x, q0.y, q0.z, q0.w, q1.x, q1.y, q1.z, q1.w,
                            q2.x, q2.y, q2.z, q2.w};
            float2 dd = make_float2(0.f, 0.f), aa = make_float2(0.f, 0.f);
#pragma unroll
            for (int m = 0; m < 8; m++) {
                float2 p = make_float2(xx[m], xx[m + 2]);
                dd = fma2(F.wH2[7 - m], p, dd);
                aa = fma2(F.hH2[7 - m], p, aa);
            }
            *(float4*)&sda[rr][2 * jp] = make_float4(dd.x, aa.x, dd.y, aa.y);
        }
    }
    __syncthreads();

    const float alpha = *pA, bp = *pBp, bm = *pBm;
    const int tx = lane, ty = wid;
    const int j = j0 + tx;
    const long ldflat = 3L * s2;
    float2 v[14];
#pragma unroll
    for (int m = 0; m < 14; m++) v[m] = sda[8 * ty + m][tx];
#pragma unroll
    for (int k = 0; k < 4; k++) {
        float2 e1 = make_float2(0.f, 0.f), e2 = make_float2(0.f, 0.f);
#pragma unroll
        for (int m = 0; m < 8; m++) {
            float2 da = v[2 * k + m];
            e1 = fma2(F.wV2[7 - m], da, e1);
            e2 = fma2(F.hV2[7 - m], da, e2);
        }
        const int i = i0 + 4 * ty + k;
        const long ro = (long)i * ldflat;
        flatb[ro + j]          = thrf(e1.x, alpha, bp, bm);
        flatb[ro + s2 + j]     = thrf(e2.x, alpha, bp, bm);
        flatb[ro + 2 * s2 + j] = thrf(e1.y, alpha, bp, bm);
        LL[(long)i * ldll + j] = thrLL ? thrf(e2.y, alpha, bp, bm) : e2.y;
    }
}

// ----------------------------------------------------------------------------
// bwd combine kernel: X = rowrecon( H (precomputed), colrecon(lh, ap) ).
// Split scalar smem (shH / shL) -> no stride-8 half-utilization wavefronts.
// ----------------------------------------------------------------------------
__global__ __launch_bounds__(256)
void bwd_final(const float* __restrict__ base,
               const float* __restrict__ ap, long lda,
               const float* __restrict__ Hb,
               int s2,
               float* __restrict__ X, long ldx,
               const float* __restrict__ hHp, const float* __restrict__ hVp)
{
    __shared__ float2 scl[36][37];     // (lh, ap)
    __shared__ float shH[64][40];      // H (column-recon of hh,hl; precomputed)
    __shared__ float shL[64][40];      // L (column-recon of lh,ap; computed here)
    __shared__ Filt F;
    const int tid = threadIdx.x;
    const int wid = tid >> 5, lane = tid & 31;
    filt_load(F, hHp, hVp, tid);

    const int i0 = blockIdx.y << 6, j0 = blockIdx.x << 6;
    const int mask = s2 - 1;
    const long ldc = 3L * s2;
    const int rbb = i0 >> 1, cbb = j0 >> 1;

    // load (lh, ap) coeff tiles (float2 interleave; full-utilization stores)
#pragma unroll
    for (int k = 0; k < 6; k++) {
        const int t = tid + 256 * k;
        if (t < 36 * 36) {
            const int rr = t / 36, cc = t - rr * 36;
            const int gr = (rbb + rr) & mask, gc = (cbb + cc) & mask;
            scl[rr][cc] = make_float2(base[(long)gr * ldc + 2 * s2 + gc],
                                      ap[(long)gr * lda + gc]);
        }
    }
    // load H tile (scalar array: stride-4B writes, full utilization)
#pragma unroll
    for (int k = 0; k < 9; k++) {
        const int t = tid + 256 * k;
        if (t < 64 * 36) {
            const int r = t / 36, cc = t - r * 36;
            shH[r][cc] = Hb[(long)(i0 + r) * s2 + ((cbb + cc) & mask)];
        }
    }
    __syncthreads();

    // column reconstruction of L: paired output rows; scalar stores
#pragma unroll
    for (int k = 0; k < 5; k++) {
        const int t = tid + 256 * k;
        if (t < 32 * 36) {
            const int m = t / 36, cc = t - m * 36;
            float2 c0 = scl[m][cc], c1 = scl[m + 1][cc], c2 = scl[m + 2][cc],
                   c3 = scl[m + 3][cc], c4 = scl[m + 4][cc];
            float2 he = make_float2(0.f, 0.f), ho = make_float2(0.f, 0.f);
            he = fma2(F.cve[0], c0, he); he = fma2(F.cve[1], c1, he);
            he = fma2(F.cve[2], c2, he); he = fma2(F.cve[3], c3, he);
            ho = fma2(F.cvo[0], c1, ho); ho = fma2(F.cvo[1], c2, ho);
            ho = fma2(F.cvo[2], c3, ho); ho = fma2(F.cvo[3], c4, ho);
            shL[2 * m][cc]     = he.x + he.y;
            shL[2 * m + 1][cc] = ho.x + ho.y;
        }
    }
    __syncthreads();

    // row reconstruction: stride-1 scalar loads (1 wavefront each)
#pragma unroll
    for (int k = 0; k < 8; k++) {
        const int r = wid + 8 * k;
        float h0 = shH[r][lane],     h1 = shH[r][lane + 1], h2 = shH[r][lane + 2],
              h3 = shH[r][lane + 3], h4 = shH[r][lane + 4];
        float l0 = shL[r][lane],     l1 = shL[r][lane + 1], l2 = shL[r][lane + 2],
              l3 = shL[r][lane + 3], l4 = shL[r][lane + 4];
        float2 v;
        v.x = F.wH[0] * h0 + F.wH[2] * h1 + F.wH[4] * h2 + F.wH[6] * h3
            + F.hH[0] * l0 + F.hH[2] * l1 + F.hH[4] * l2 + F.hH[6] * l3;
        v.y = F.wH[1] * h1 + F.wH[3] * h2 + F.wH[5] * h3 + F.wH[7] * h4
            + F.hH[1] * l1 + F.hH[3] * l2 + F.hH[5] * l3 + F.hH[7] * l4;
        *(float2*)&X[(long)(i0 + r) * ldx + (j0 + 2 * lane)] = v;
    }
}

// ----------------------------------------------------------------------------
// Group C: H = colrecon(hh, hl) tiles over [start : stride : end).
// ----------------------------------------------------------------------------
__device__ void colrecon_tiles(float* pool, const Filt& F,
                               const float* __restrict__ base, int s2,
                               float* __restrict__ H,
                               int start, int stride, int endT)
{
    float2 (*sc1)[33] = reinterpret_cast<float2(*)[33]>(pool);
    float2 (*sc2)[33] = reinterpret_cast<float2(*)[33]>(pool + 36 * 33 * 2);
    const int tid = threadIdx.x;
    const int mask = s2 - 1;
    const long ldc = 3L * s2;
    const int ntj = s2 / 64;

    for (int t = start; t < endT; t += stride) {
        const int by = t / ntj, bx = t - by * ntj;
        const int i0 = by * 64, j0 = bx * 64;
        const int rbb = i0 >> 1;
#pragma unroll
        for (int k = 0; k < 5; k++) {
            const int idx = tid + 256 * k;
            if (idx < 36 * 32) {
                const int rr = idx >> 5, c2 = idx & 31;
                const int gr = (rbb + rr) & mask;
                const long o = (long)gr * ldc + j0 + 2 * c2;
                sc1[rr][c2] = *(const float2*)&base[o];
                sc2[rr][c2] = *(const float2*)&base[o + s2];
            }
        }
        __syncthreads();
#pragma unroll
        for (int k = 0; k < 4; k++) {
            const int idx = tid + 256 * k;
            if (idx < 32 * 32) {
                const int m = idx >> 5, c2 = idx & 31;
                float2 c1v[5], c2v[5];
#pragma unroll
                for (int u = 0; u < 5; u++) { c1v[u] = sc1[m + u][c2]; c2v[u] = sc2[m + u][c2]; }
                float2 he = make_float2(0.f, 0.f), ho = make_float2(0.f, 0.f);
#pragma unroll
                for (int u = 0; u < 4; u++) {
                    he = fma2(F.wV2[2 * u],     c1v[u],     he);
                    he = fma2(F.hV2[2 * u],     c2v[u],     he);
                    ho = fma2(F.wV2[2 * u + 1], c1v[u + 1], ho);
                    ho = fma2(F.hV2[2 * u + 1], c2v[u + 1], ho);
                }
                *(float2*)&H[(long)(i0 + 2 * m)     * s2 + j0 + 2 * c2] = he;
                *(float2*)&H[(long)(i0 + 2 * m + 1) * s2 + j0 + 2 * c2] = ho;
            }
        }
        __syncthreads();
    }
}

// ----------------------------------------------------------------------------
// Tail device functions (R8).
// ----------------------------------------------------------------------------
template<int TI>
__device__ void fwd_tiles(float* pool, const Filt& F,
                          const float* __restrict__ X, int s, long ldx,
                          float* __restrict__ flatb,
                          float* __restrict__ LL, long ldll, int thrLL,
                          float alpha, float bp, float bm, int nb)
{
    constexpr int NW = 2 * TI + 6;
    constexpr int C4 = NW / 4 + 2;
    float4 (*sx4)[C4] = reinterpret_cast<float4(*)[C4]>(pool);
    float2 (*sda)[TI + 2] = reinterpret_cast<float2(*)[TI + 2]>(pool + NW * C4 * 4);
    const int s2 = s >> 1;
    const int nt = s2 / TI;
    const int mask = s - 1;
    const int tid = threadIdx.x;
    const long ldflat = 3L * s2;
    constexpr int TIH = TI / 2;
    constexpr int NL1 = (NW * NW + 255) / 256;
    constexpr int NL2 = (NW * TIH + 255) / 256;
    constexpr int NL3 = (TI * TI + 255) / 256;

    for (int tile = blockIdx.x; tile < nt * nt; tile += nb) {
        const int by = tile / nt, bx = tile - by * nt;
        const int i0 = by * TI, j0 = bx * TI;
        const int rb = 2 * i0 - 7, cb = 2 * j0 - 7;
#pragma unroll
        for (int k = 0; k < NL1; k++) {
            const int t = tid + 256 * k;
            if (t < NW * NW) {
                const int rr = t / NW, cc = t - rr * NW;
                ((float*)(&sx4[rr][0]))[cc] =
                    X[(long)((rb + rr) & mask) * ldx + ((cb + cc) & mask)];
            }
        }
        __syncthreads();
#pragma unroll
        for (int k = 0; k < NL2; k++) {
            const int t = tid + 256 * k;
            if (t < NW * TIH) {
                const int rr = t / TIH, jp = t - rr * TIH;
                float4 q0 = sx4[rr][jp], q1 = sx4[rr][jp + 1], q2 = sx4[rr][jp + 2];
                float xx[12] = {q0.x, q0.y, q0.z, q0.w, q1.x, q1.y, q1.z, q1.w,
                                q2.x, q2.y, q2.z, q2.w};
                float2 dd = make_float2(0.f, 0.f), aa = make_float2(0.f, 0.f);
#pragma unroll
                for (int m = 0; m < 8; m++) {
                    float2 p = make_float2(xx[m], xx[m + 2]);
                    dd = fma2(F.wH2[7 - m], p, dd);
                    aa = fma2(F.hH2[7 - m], p, aa);
                }
                *(float4*)&sda[rr][2 * jp] = make_float4(dd.x, aa.x, dd.y, aa.y);
            }
        }
        __syncthreads();
#pragma unroll
        for (int k = 0; k < NL3; k++) {
            const int t = tid + 256 * k;
            if (t < TI * TI) {
                const int tx = t % TI, il = t / TI;
                const int i = i0 + il, j = j0 + tx;
                float2 e1 = make_float2(0.f, 0.f), e2 = make_float2(0.f, 0.f);
#pragma unroll
                for (int m = 0; m < 8; m++) {
                    float2 da = sda[2 * il + m][tx];
                    e1 = fma2(F.wV2[7 - m], da, e1);
                    e2 = fma2(F.hV2[7 - m], da, e2);
                }
                const long ro = (long)i * ldflat;
                flatb[ro + j]          = thrf(e1.x, alpha, bp, bm);
                flatb[ro + s2 + j]     = thrf(e2.x, alpha, bp, bm);
                flatb[ro + 2 * s2 + j] = thrf(e1.y, alpha, bp, bm);
                LL[(long)i * ldll + j] = thrLL ? thrf(e2.y, alpha, bp, bm) : e2.y;
            }
        }
        __syncthreads();
    }
}

template<int TO>
__device__ void bwd_tiles(float* pool, const Filt& F,
                          const float* __restrict__ base,
                          const float* __restrict__ ap, long lda,
                          int s2, float* __restrict__ X, long ldx, int nb)
{
    constexpr int NC = TO / 2 + 4;
    constexpr int LDC = NC + 1;
    float2 (*sc1)[LDC] = reinterpret_cast<float2(*)[LDC]>(pool);
    float2 (*sc2)[LDC] = reinterpret_cast<float2(*)[LDC]>(pool + 2 * NC * LDC);
    float2 (*sh2)[LDC] = reinterpret_cast<float2(*)[LDC]>(pool + 4 * NC * LDC);
    const int nt = (2 * s2) / TO;
    const int mask = s2 - 1;
    const long ldc = 3L * s2;
    const int tid = threadIdx.x;
    constexpr int NL1 = (NC * NC + 255) / 256;
    constexpr int NL2 = ((TO / 2) * NC + 255) / 256;
    constexpr int NL3 = (TO * (TO / 2) + 255) / 256;

    for (int tile = blockIdx.x; tile < nt * nt; tile += nb) {
        const int by = tile / nt, bx = tile - by * nt;
        const int i0 = by * TO, j0 = bx * TO;
        const int rbb = i0 >> 1, cbb = j0 >> 1;
#pragma unroll
        for (int k = 0; k < NL1; k++) {
            const int t = tid + 256 * k;
            if (t < NC * NC) {
                const int rr = t / NC, cc = t - rr * NC;
                const int gr = (rbb + rr) & mask, gc = (cbb + cc) & mask;
                const long o = (long)gr * ldc + gc;
                sc1[rr][cc] = make_float2(base[o],      base[o + 2 * s2]);
                sc2[rr][cc] = make_float2(base[o + s2], ap[(long)gr * lda + gc]);
            }
        }
        __syncthreads();
#pragma unroll
        for (int k = 0; k < NL2; k++) {
            const int t = tid + 256 * k;
            if (t < (TO / 2) * NC) {
                const int m = t / NC, cc = t - m * NC;
                float2 c1[5], c2[5];
#pragma unroll
                for (int u = 0; u < 5; u++) { c1[u] = sc1[m + u][cc]; c2[u] = sc2[m + u][cc]; }
                float2 he = make_float2(0.f, 0.f), ho = make_float2(0.f, 0.f);
#pragma unroll
                for (int u = 0; u < 4; u++) {
                    he = fma2(F.wV2[2 * u],     c1[u],     he);
                    he = fma2(F.hV2[2 * u],     c2[u],     he);
                    ho = fma2(F.wV2[2 * u + 1], c1[u + 1], ho);
                    ho = fma2(F.hV2[2 * u + 1], c2[u + 1], ho);
                }
                sh2[2 * m][cc]     = he;
                sh2[2 * m + 1][cc] = ho;
            }
        }
        __syncthreads();
#pragma unroll
        for (int k = 0; k < NL3; k++) {
            const int t = tid + 256 * k;
            if (t < TO * (TO / 2)) {
                const int c2 = t % (TO / 2), r = t / (TO / 2);
                float2 q0 = sh2[r][c2], q1 = sh2[r][c2 + 1], q2 = sh2[r][c2 + 2],
                       q3 = sh2[r][c2 + 3], q4 = sh2[r][c2 + 4];
                float2 ae = make_float2(0.f, 0.f), ao = make_float2(0.f, 0.f);
                ae = fma2(F.cxe[0], q0, ae); ae = fma2(F.cxe[1], q1, ae);
                ae = fma2(F.cxe[2], q2, ae); ae = fma2(F.cxe[3], q3, ae);
                ao = fma2(F.cxo[0], q1, ao); ao = fma2(F.cxo[1], q2, ao);
                ao = fma2(F.cxo[2], q3, ao); ao = fma2(F.cxo[3], q4, ao);
                float2 v;
                v.x = ae.x + ae.y;
                v.y = ao.x + ao.y;
                *(float2*)&X[(long)(i0 + r) * ldx + (j0 + 2 * c2)] = v;
            }
        }
        __syncthreads();
    }
}

// ----------------------------------------------------------------------------
// MEGA kernel: group D (blocks [0,ND)) = tail; group C = H0 + H1 precompute.
// ----------------------------------------------------------------------------
__global__ __launch_bounds__(256, 4)
void mega(float* bufA, float* bufB, float* flat, float* H0, float* H1,
          const float* __restrict__ scal,
          const float* pA, const float* pBp, const float* pBm)
{
    __shared__ __align__(16) float pool[4864];
    __shared__ Filt F;
    const int tid = threadIdx.x;
    const size_t levoff[6] = {0, 12582912, 15728640, 16515072, 16711680, 16760832};

    if (blockIdx.x < ND) {
        const float alpha = *pA, bp = *pBp, bm = *pBm;
        unsigned bc = 0;
        const float* cur = bufB;
        long ldcur = 1024;
        int s = 1024;
        for (int lev = 2; lev <= 5; lev++) {
            filt_load(F, scal + lev * 8, scal + (lev + 1) * 8, tid);
            const int s2 = s >> 1;
            float* fb = flat + levoff[lev];
            float* ll; long ldll; int thr;
            if (lev == 5) { ll = flat + 16773120; ldll = 64; thr = 1; }
            else          { ll = (lev & 1) ? bufB : bufA; ldll = s2; thr = 0; }
            if (lev == 2)
                fwd_tiles<16>(pool, F, cur, s, ldcur, fb, ll, ldll, thr, alpha, bp, bm, ND);
            else
                fwd_tiles<8>(pool, F, cur, s, ldcur, fb, ll, ldll, thr, alpha, bp, bm, ND);
            cur = ll; ldcur = ldll; s = s2;
            bc++; grid_barrier(&g_bar, bc * (unsigned)ND);
        }
        const float* aprev = flat + 16773120;
        long lda = 64;
        for (int lev = 5; lev >= 2; lev--) {
            filt_load(F, scal + lev * 8, scal + (lev + 1) * 8, tid);
            const int s2 = 2048 >> lev;
            const float* base = flat + levoff[lev];
            float* xo = (lev & 1) ? bufB : bufA;
            long ldx = 2 * s2;
            if (lev == 2)
                bwd_tiles<32>(pool, F, base, aprev, lda, s2, xo, ldx, ND);
            else
                bwd_tiles<16>(pool, F, base, aprev, lda, s2, xo, ldx, ND);
            aprev = xo; lda = ldx;
            if (lev > 2) { bc++; grid_barrier(&g_bar, bc * (unsigned)ND); }
        }
    } else {
        const int cb = blockIdx.x - ND;
        const int nc = NB_MEGA - ND;
        // H0: lev0, vertical filter = scal + 8
        filt_load(F, scal, scal + 8, tid);
        colrecon_tiles(pool, F, flat, 2048, H0, cb, nc, 2048);
        __syncthreads();
        // H1: lev1, vertical filter = scal + 16
        filt_load(F, scal + 8, scal + 16, tid);
        colrecon_tiles(pool, F, flat + 12582912, 1024, H1, cb, nc, 512);
    }
}

// ----------------------------------------------------------------------------
// Host orchestration (graph-capturable: kernel launches only).
// ----------------------------------------------------------------------------
extern "C" void kernel_launch(void* const* d_in, const int* in_sizes, int n_in,
                              void* d_out, int out_size)
{
    const float* x    = (const float*)d_in[0];
    const float* scal = (const float*)d_in[1];
    const float* pA   = (const float*)d_in[2];
    const float* pBp  = (const float*)d_in[3];
    const float* pBm  = (const float*)d_in[4];

    float* out  = (float*)d_out;
    float* flat = out + (size_t)NSIDE * NSIDE;

    float *bufA, *bufB, *Hbuf;
    cudaGetSymbolAddress((void**)&bufA, g_bufA);
    cudaGetSymbolAddress((void**)&bufB, g_bufB);
    cudaGetSymbolAddress((void**)&Hbuf, g_H);
    float* H0 = Hbuf;
    float* H1 = Hbuf + 4096u * 2048u;

    // forward level 0: x (4096) -> flat lev0 + bufA (2048)  [resets g_bar]
    fwd2d32<<<dim3(64, 64), 256>>>(x, 4096, 4096,
                                   flat, bufA, 2048, 0,
                                   scal, scal + 8, pA, pBp, pBm);
    // forward level 1: bufA (2048) -> flat lev1 + bufB (1024)
    fwd2d32<<<dim3(32, 32), 256>>>(bufA, 2048, 2048,
                                   flat + 12582912, bufB, 1024, 0,
                                   scal + 8, scal + 16, pA, pBp, pBm);
    // mega: tail (-> bufA 1024) || H0/H1 precompute
    mega<<<NB_MEGA, 256>>>(bufA, bufB, flat, H0, H1, scal, pA, pBp, pBm);

    // backward level 1 combine: H1 + colrecon(lh1, bufA) -> bufB (2048)
    bwd_final<<<dim3(32, 32), 256>>>(flat + 12582912, bufA, 1024,
                                     H1, 1024, bufB, 2048,
                                     scal + 8, scal + 16);
    // backward level 0 combine: H0 + colrecon(lh0, bufB) -> out (4096)
    bwd_final<<<dim3(64, 64), 256>>>(flat, bufB, 2048,
                                     H0, 2048, out, 4096,
                                     scal, scal + 8);
}

// round 15
// speedup vs baseline: 1.0480x; 1.0480x over previous
#include <cuda_runtime.h>

// ----------------------------------------------------------------------------
// Despawn2D: 6-level 2D db4 circular DWT + sigmoid threshold + inverse DWT.
// fwd0, fwd1: fused tiled kernels (R8-proven; fwd0 block(0,0) resets g_bar).
// mega: blocks [0,ND) run lev2..5 fwd + 5..2 bwd tail (grid barriers);
//       blocks [ND,512) precompute H0/H1 = colrecon(hh,hl) for levels 0/1.
//       ND=384: tail is the binding side (measured), so it gets more blocks.
// bwd1, bwd0: combine kernels (H + colrecon(lh,approx) -> row recon).
// d_out layout: [ recon (4096*4096) | flat coeffs (4096*4096) ]
// flat per level: (s2, 3*s2) row-major hh|hl|lh, then approx (64*64) last.
// ----------------------------------------------------------------------------

#define NSIDE 4096
#define NB_MEGA 512
#define ND 384

__device__ float g_bufA[2048u * 2048u];
__device__ float g_bufB[2048u * 2048u];
__device__ float g_H[4096u * 2048u + 2048u * 1024u];   // H0 (32MB) + H1 (8MB)
__device__ unsigned g_bar;

__device__ __forceinline__ float2 fma2(float2 a, float2 b, float2 c)
{
    float2 d;
    asm("fma.rn.f32x2 %0, %1, %2, %3;"
        : "=l"(reinterpret_cast<unsigned long long&>(d))
        : "l"(reinterpret_cast<unsigned long long&>(a)),
          "l"(reinterpret_cast<unsigned long long&>(b)),
          "l"(reinterpret_cast<unsigned long long&>(c)));
    return d;
}

__device__ __forceinline__ float thrf(float t, float a, float bp, float bm)
{
    float s1 = 1.0f / (1.0f + __expf(-a * (t - bp)));
    float s2 = 1.0f / (1.0f + __expf( a * (t + bm)));
    return t * (s1 + s2);
}

__device__ __forceinline__ void grid_barrier(unsigned* cnt, unsigned target)
{
    __syncthreads();
    if (threadIdx.x == 0) {
        __threadfence();
        atomicAdd(cnt, 1u);
        while (*((volatile unsigned*)cnt) < target) { __nanosleep(64); }
        __threadfence();
    }
    __syncthreads();
}

struct Filt {
    float hH[8], wH[8], hV[8], wV[8];
    float2 hH2[8], wH2[8], hV2[8], wV2[8];
    float2 cxe[4], cxo[4];
    float2 cve[4], cvo[4];
};

__device__ __forceinline__ void filt_load(Filt& F, const float* hHp, const float* hVp, int tid)
{
    if (tid < 8) { F.hH[tid] = hHp[tid]; F.hV[tid] = hVp[tid]; }
    __syncthreads();
    if (tid < 8) {
        float s = (tid & 1) ? -1.0f : 1.0f;
        float wh = F.hH[7 - tid] * s;
        float wv = F.hV[7 - tid] * s;
        F.wH[tid] = wh;           F.wV[tid] = wv;
        F.hH2[tid] = make_float2(F.hH[tid], F.hH[tid]);
        F.wH2[tid] = make_float2(wh, wh);
        F.hV2[tid] = make_float2(F.hV[tid], F.hV[tid]);
        F.wV2[tid] = make_float2(wv, wv);
    }
    __syncthreads();
    if (tid < 4) {
        F.cxe[tid] = make_float2(F.wH[2 * tid],     F.hH[2 * tid]);
        F.cxo[tid] = make_float2(F.wH[2 * tid + 1], F.hH[2 * tid + 1]);
        F.cve[tid] = make_float2(F.wV[2 * tid],     F.hV[2 * tid]);
        F.cvo[tid] = make_float2(F.wV[2 * tid + 1], F.hV[2 * tid + 1]);
    }
    __syncthreads();
}

// ----------------------------------------------------------------------------
// Big fused forward (TI=32). R8-proven scalar high-MLP loads.
// Block (0,0) resets g_bar (graph-safe: stream-ordered before mega).
// ----------------------------------------------------------------------------
__global__ __launch_bounds__(256)
void fwd2d32(const float* __restrict__ X, int s, long ldx,
             float* __restrict__ flatb,
             float* __restrict__ LL, long ldll, int thrLL,
             const float* __restrict__ hHp, const float* __restrict__ hVp,
             const float* __restrict__ pA, const float* __restrict__ pBp,
             const float* __restrict__ pBm)
{
    __shared__ __align__(16) float4 sx4[70][19];
    __shared__ __align__(16) float2 sda[70][34];
    __shared__ Filt F;
    const int tid = threadIdx.x;
    const int wid = tid >> 5, lane = tid & 31;
    if (tid == 0 && blockIdx.x == 0 && blockIdx.y == 0) g_bar = 0;
    filt_load(F, hHp, hVp, tid);

    const int s2 = s >> 1;
    const int i0 = blockIdx.y << 5, j0 = blockIdx.x << 5;
    const int mask = s - 1;
    const int rb = 2 * i0 - 7, cb = 2 * j0 - 7;

#pragma unroll
    for (int k = 0; k < 9; k++) {
        const int rr = wid + 8 * k;
        if (rr < 70) {
            const float* xr = X + (long)((rb + rr) & mask) * ldx;
            float* dst = (float*)(&sx4[rr][0]);
#pragma unroll
            for (int cc = 0; cc < 3; cc++) {
                const int c = lane + 32 * cc;
                if (c < 70) dst[c] = xr[(cb + c) & mask];
            }
        }
    }
    __syncthreads();

#pragma unroll
    for (int k = 0; k < 5; k++) {
        const int t = tid + 256 * k;
        if (t < 70 * 16) {
            const int rr = t >> 4, jp = t & 15;
            float4 q0 = sx4[rr][jp], q1 = sx4[rr][jp + 1], q2 = sx4[rr][jp + 2];
            float xx[12] = {q0.x, q0.y, q0.z, q0.w, q1.x, q1.y, q1.z, q1.w,
                            q2.x, q2.y, q2.z, q2.w};
            float2 dd = make_float2(0.f, 0.f), aa = make_float2(0.f, 0.f);
#pragma unroll
            for (int m = 0; m < 8; m++) {
                float2 p = make_float2(xx[m], xx[m + 2]);
                dd = fma2(F.wH2[7 - m], p, dd);
                aa = fma2(F.hH2[7 - m], p, aa);
            }
            *(float4*)&sda[rr][2 * jp] = make_float4(dd.x, aa.x, dd.y, aa.y);
        }
    }
    __syncthreads();

    const float alpha = *pA, bp = *pBp, bm = *pBm;
    const int tx = lane, ty = wid;
    const int j = j0 + tx;
    const long ldflat = 3L * s2;
    float2 v[14];
#pragma unroll
    for (int m = 0; m < 14; m++) v[m] = sda[8 * ty + m][tx];
#pragma unroll
    for (int k = 0; k < 4; k++) {
        float2 e1 = make_float2(0.f, 0.f), e2 = make_float2(0.f, 0.f);
#pragma unroll
        for (int m = 0; m < 8; m++) {
            float2 da = v[2 * k + m];
            e1 = fma2(F.wV2[7 - m], da, e1);
            e2 = fma2(F.hV2[7 - m], da, e2);
        }
        const int i = i0 + 4 * ty + k;
        const long ro = (long)i * ldflat;
        flatb[ro + j]          = thrf(e1.x, alpha, bp, bm);
        flatb[ro + s2 + j]     = thrf(e2.x, alpha, bp, bm);
        flatb[ro + 2 * s2 + j] = thrf(e1.y, alpha, bp, bm);
        LL[(long)i * ldll + j] = thrLL ? thrf(e2.y, alpha, bp, bm) : e2.y;
    }
}

// ----------------------------------------------------------------------------
// bwd combine kernel: X = rowrecon( H (precomputed), colrecon(lh, ap) ).
// (R13-proven float2 sh2 version.)
// ----------------------------------------------------------------------------
__global__ __launch_bounds__(256)
void bwd_final(const float* __restrict__ base,
               const float* __restrict__ ap, long lda,
               const float* __restrict__ Hb,
               int s2,
               float* __restrict__ X, long ldx,
               const float* __restrict__ hHp, const float* __restrict__ hVp)
{
    __shared__ float2 scl[36][37];
    __shared__ float2 sh2[64][37];
    __shared__ Filt F;
    const int tid = threadIdx.x;
    const int wid = tid >> 5, lane = tid & 31;
    filt_load(F, hHp, hVp, tid);

    const int i0 = blockIdx.y << 6, j0 = blockIdx.x << 6;
    const int mask = s2 - 1;
    const long ldc = 3L * s2;
    const int rbb = i0 >> 1, cbb = j0 >> 1;

#pragma unroll
    for (int k = 0; k < 6; k++) {
        const int t = tid + 256 * k;
        if (t < 36 * 36) {
            const int rr = t / 36, cc = t - rr * 36;
            const int gr = (rbb + rr) & mask, gc = (cbb + cc) & mask;
            scl[rr][cc] = make_float2(base[(long)gr * ldc + 2 * s2 + gc],
                                      ap[(long)gr * lda + gc]);
        }
    }
#pragma unroll
    for (int k = 0; k < 9; k++) {
        const int t = tid + 256 * k;
        if (t < 64 * 36) {
            const int r = t / 36, cc = t - r * 36;
            sh2[r][cc].x = Hb[(long)(i0 + r) * s2 + ((cbb + cc) & mask)];
        }
    }
    __syncthreads();

#pragma unroll
    for (int k = 0; k < 5; k++) {
        const int t = tid + 256 * k;
        if (t < 32 * 36) {
            const int m = t / 36, cc = t - m * 36;
            float2 c0 = scl[m][cc], c1 = scl[m + 1][cc], c2 = scl[m + 2][cc],
                   c3 = scl[m + 3][cc], c4 = scl[m + 4][cc];
            float2 he = make_float2(0.f, 0.f), ho = make_float2(0.f, 0.f);
            he = fma2(F.cve[0], c0, he); he = fma2(F.cve[1], c1, he);
            he = fma2(F.cve[2], c2, he); he = fma2(F.cve[3], c3, he);
            ho = fma2(F.cvo[0], c1, ho); ho = fma2(F.cvo[1], c2, ho);
            ho = fma2(F.cvo[2], c3, ho); ho = fma2(F.cvo[3], c4, ho);
            sh2[2 * m][cc].y     = he.x + he.y;
            sh2[2 * m + 1][cc].y = ho.x + ho.y;
        }
    }
    __syncthreads();

#pragma unroll
    for (int k = 0; k < 8; k++) {
        const int r = wid + 8 * k;
        float2 q0 = sh2[r][lane], q1 = sh2[r][lane + 1], q2 = sh2[r][lane + 2],
               q3 = sh2[r][lane + 3], q4 = sh2[r][lane + 4];
        float2 ae = make_float2(0.f, 0.f), ao = make_float2(0.f, 0.f);
        ae = fma2(F.cxe[0], q0, ae); ae = fma2(F.cxe[1], q1, ae);
        ae = fma2(F.cxe[2], q2, ae); ae = fma2(F.cxe[3], q3, ae);
        ao = fma2(F.cxo[0], q1, ao); ao = fma2(F.cxo[1], q2, ao);
        ao = fma2(F.cxo[2], q3, ao); ao = fma2(F.cxo[3], q4, ao);
        float2 v;
        v.x = ae.x + ae.y;
        v.y = ao.x + ao.y;
        *(float2*)&X[(long)(i0 + r) * ldx + (j0 + 2 * lane)] = v;
    }
}

// ----------------------------------------------------------------------------
// Group C: H = colrecon(hh, hl) tiles over [start : stride : end).
// ----------------------------------------------------------------------------
__device__ void colrecon_tiles(float* pool, const Filt& F,
                               const float* __restrict__ base, int s2,
                               float* __restrict__ H,
                               int start, int stride, int endT)
{
    float2 (*sc1)[33] = reinterpret_cast<float2(*)[33]>(pool);
    float2 (*sc2)[33] = reinterpret_cast<float2(*)[33]>(pool + 36 * 33 * 2);
    const int tid = threadIdx.x;
    const int mask = s2 - 1;
    const long ldc = 3L * s2;
    const int ntj = s2 / 64;

    for (int t = start; t < endT; t += stride) {
        const int by = t / ntj, bx = t - by * ntj;
        const int i0 = by * 64, j0 = bx * 64;
        const int rbb = i0 >> 1;
#pragma unroll
        for (int k = 0; k < 5; k++) {
            const int idx = tid + 256 * k;
            if (idx < 36 * 32) {
                const int rr = idx >> 5, c2 = idx & 31;
                const int gr = (rbb + rr) & mask;
                const long o = (long)gr * ldc + j0 + 2 * c2;
                sc1[rr][c2] = *(const float2*)&base[o];
                sc2[rr][c2] = *(const float2*)&base[o + s2];
            }
        }
        __syncthreads();
#pragma unroll
        for (int k = 0; k < 4; k++) {
            const int idx = tid + 256 * k;
            if (idx < 32 * 32) {
                const int m = idx >> 5, c2 = idx & 31;
                float2 c1v[5], c2v[5];
#pragma unroll
                for (int u = 0; u < 5; u++) { c1v[u] = sc1[m + u][c2]; c2v[u] = sc2[m + u][c2]; }
                float2 he = make_float2(0.f, 0.f), ho = make_float2(0.f, 0.f);
#pragma unroll
                for (int u = 0; u < 4; u++) {
                    he = fma2(F.wV2[2 * u],     c1v[u],     he);
                    he = fma2(F.hV2[2 * u],     c2v[u],     he);
                    ho = fma2(F.wV2[2 * u + 1], c1v[u + 1], ho);
                    ho = fma2(F.hV2[2 * u + 1], c2v[u + 1], ho);
                }
                *(float2*)&H[(long)(i0 + 2 * m)     * s2 + j0 + 2 * c2] = he;
                *(float2*)&H[(long)(i0 + 2 * m + 1) * s2 + j0 + 2 * c2] = ho;
            }
        }
        __syncthreads();
    }
}

// ----------------------------------------------------------------------------
// Tail device functions (R8).
// ----------------------------------------------------------------------------
template<int TI>
__device__ void fwd_tiles(float* pool, const Filt& F,
                          const float* __restrict__ X, int s, long ldx,
                          float* __restrict__ flatb,
                          float* __restrict__ LL, long ldll, int thrLL,
                          float alpha, float bp, float bm, int nb)
{
    constexpr int NW = 2 * TI + 6;
    constexpr int C4 = NW / 4 + 2;
    float4 (*sx4)[C4] = reinterpret_cast<float4(*)[C4]>(pool);
    float2 (*sda)[TI + 2] = reinterpret_cast<float2(*)[TI + 2]>(pool + NW * C4 * 4);
    const int s2 = s >> 1;
    const int nt = s2 / TI;
    const int mask = s - 1;
    const int tid = threadIdx.x;
    const long ldflat = 3L * s2;
    constexpr int TIH = TI / 2;
    constexpr int NL1 = (NW * NW + 255) / 256;
    constexpr int NL2 = (NW * TIH + 255) / 256;
    constexpr int NL3 = (TI * TI + 255) / 256;

    for (int tile = blockIdx.x; tile < nt * nt; tile += nb) {
        const int by = tile / nt, bx = tile - by * nt;
        const int i0 = by * TI, j0 = bx * TI;
        const int rb = 2 * i0 - 7, cb = 2 * j0 - 7;
#pragma unroll
        for (int k = 0; k < NL1; k++) {
            const int t = tid + 256 * k;
            if (t < NW * NW) {
                const int rr = t / NW, cc = t - rr * NW;
                ((float*)(&sx4[rr][0]))[cc] =
                    X[(long)((rb + rr) & mask) * ldx + ((cb + cc) & mask)];
            }
        }
        __syncthreads();
#pragma unroll
        for (int k = 0; k < NL2; k++) {
            const int t = tid + 256 * k;
            if (t < NW * TIH) {
                const int rr = t / TIH, jp = t - rr * TIH;
                float4 q0 = sx4[rr][jp], q1 = sx4[rr][jp + 1], q2 = sx4[rr][jp + 2];
                float xx[12] = {q0.x, q0.y, q0.z, q0.w, q1.x, q1.y, q1.z, q1.w,
                                q2.x, q2.y, q2.z, q2.w};
                float2 dd = make_float2(0.f, 0.f), aa = make_float2(0.f, 0.f);
#pragma unroll
                for (int m = 0; m < 8; m++) {
                    float2 p = make_float2(xx[m], xx[m + 2]);
                    dd = fma2(F.wH2[7 - m], p, dd);
                    aa = fma2(F.hH2[7 - m], p, aa);
                }
                *(float4*)&sda[rr][2 * jp] = make_float4(dd.x, aa.x, dd.y, aa.y);
            }
        }
        __syncthreads();
#pragma unroll
        for (int k = 0; k < NL3; k++) {
            const int t = tid + 256 * k;
            if (t < TI * TI) {
                const int tx = t % TI, il = t / TI;
                const int i = i0 + il, j = j0 + tx;
                float2 e1 = make_float2(0.f, 0.f), e2 = make_float2(0.f, 0.f);
#pragma unroll
                for (int m = 0; m < 8; m++) {
                    float2 da = sda[2 * il + m][tx];
                    e1 = fma2(F.wV2[7 - m], da, e1);
                    e2 = fma2(F.hV2[7 - m], da, e2);
                }
                const long ro = (long)i * ldflat;
                flatb[ro + j]          = thrf(e1.x, alpha, bp, bm);
                flatb[ro + s2 + j]     = thrf(e2.x, alpha, bp, bm);
                flatb[ro + 2 * s2 + j] = thrf(e1.y, alpha, bp, bm);
                LL[(long)i * ldll + j] = thrLL ? thrf(e2.y, alpha, bp, bm) : e2.y;
            }
        }
        __syncthreads();
    }
}

template<int TO>
__device__ void bwd_tiles(float* pool, const Filt& F,
                          const float* __restrict__ base,
                          const float* __restrict__ ap, long lda,
                          int s2, float* __restrict__ X, long ldx, int nb)
{
    constexpr int NC = TO / 2 + 4;
    constexpr int LDC = NC + 1;
    float2 (*sc1)[LDC] = reinterpret_cast<float2(*)[LDC]>(pool);
    float2 (*sc2)[LDC] = reinterpret_cast<float2(*)[LDC]>(pool + 2 * NC * LDC);
    float2 (*sh2)[LDC] = reinterpret_cast<float2(*)[LDC]>(pool + 4 * NC * LDC);
    const int nt = (2 * s2) / TO;
    const int mask = s2 - 1;
    const long ldc = 3L * s2;
    const int tid = threadIdx.x;
    constexpr int NL1 = (NC * NC + 255) / 256;
    constexpr int NL2 = ((TO / 2) * NC + 255) / 256;
    constexpr int NL3 = (TO * (TO / 2) + 255) / 256;

    for (int tile = blockIdx.x; tile < nt * nt; tile += nb) {
        const int by = tile / nt, bx = tile - by * nt;
        const int i0 = by * TO, j0 = bx * TO;
        const int rbb = i0 >> 1, cbb = j0 >> 1;
#pragma unroll
        for (int k = 0; k < NL1; k++) {
            const int t = tid + 256 * k;
            if (t < NC * NC) {
                const int rr = t / NC, cc = t - rr * NC;
                const int gr = (rbb + rr) & mask, gc = (cbb + cc) & mask;
                const long o = (long)gr * ldc + gc;
                sc1[rr][cc] = make_float2(base[o],      base[o + 2 * s2]);
                sc2[rr][cc] = make_float2(base[o + s2], ap[(long)gr * lda + gc]);
            }
        }
        __syncthreads();
#pragma unroll
        for (int k = 0; k < NL2; k++) {
            const int t = tid + 256 * k;
            if (t < (TO / 2) * NC) {
                const int m = t / NC, cc = t - m * NC;
                float2 c1[5], c2[5];
#pragma unroll
                for (int u = 0; u < 5; u++) { c1[u] = sc1[m + u][cc]; c2[u] = sc2[m + u][cc]; }
                float2 he = make_float2(0.f, 0.f), ho = make_float2(0.f, 0.f);
#pragma unroll
                for (int u = 0; u < 4; u++) {
                    he = fma2(F.wV2[2 * u],     c1[u],     he);
                    he = fma2(F.hV2[2 * u],     c2[u],     he);
                    ho = fma2(F.wV2[2 * u + 1], c1[u + 1], ho);
                    ho = fma2(F.hV2[2 * u + 1], c2[u + 1], ho);
                }
                sh2[2 * m][cc]     = he;
                sh2[2 * m + 1][cc] = ho;
            }
        }
        __syncthreads();
#pragma unroll
        for (int k = 0; k < NL3; k++) {
            const int t = tid + 256 * k;
            if (t < TO * (TO / 2)) {
                const int c2 = t % (TO / 2), r = t / (TO / 2);
                float2 q0 = sh2[r][c2], q1 = sh2[r][c2 + 1], q2 = sh2[r][c2 + 2],
                       q3 = sh2[r][c2 + 3], q4 = sh2[r][c2 + 4];
                float2 ae = make_float2(0.f, 0.f), ao = make_float2(0.f, 0.f);
                ae = fma2(F.cxe[0], q0, ae); ae = fma2(F.cxe[1], q1, ae);
                ae = fma2(F.cxe[2], q2, ae); ae = fma2(F.cxe[3], q3, ae);
                ao = fma2(F.cxo[0], q1, ao); ao = fma2(F.cxo[1], q2, ao);
                ao = fma2(F.cxo[2], q3, ao); ao = fma2(F.cxo[3], q4, ao);
                float2 v;
                v.x = ae.x + ae.y;
                v.y = ao.x + ao.y;
                *(float2*)&X[(long)(i0 + r) * ldx + (j0 + 2 * c2)] = v;
            }
        }
        __syncthreads();
    }
}

// ----------------------------------------------------------------------------
// MEGA kernel: group D (blocks [0,ND)) = tail; group C = H0 + H1 precompute.
// ----------------------------------------------------------------------------
__global__ __launch_bounds__(256, 4)
void mega(float* bufA, float* bufB, float* flat, float* H0, float* H1,
          const float* __restrict__ scal,
          const float* pA, const float* pBp, const float* pBm)
{
    __shared__ __align__(16) float pool[4864];
    __shared__ Filt F;
    const int tid = threadIdx.x;
    const size_t levoff[6] = {0, 12582912, 15728640, 16515072, 16711680, 16760832};

    if (blockIdx.x < ND) {
        const float alpha = *pA, bp = *pBp, bm = *pBm;
        unsigned bc = 0;
        const float* cur = bufB;
        long ldcur = 1024;
        int s = 1024;
        for (int lev = 2; lev <= 5; lev++) {
            filt_load(F, scal + lev * 8, scal + (lev + 1) * 8, tid);
            const int s2 = s >> 1;
            float* fb = flat + levoff[lev];
            float* ll; long ldll; int thr;
            if (lev == 5) { ll = flat + 16773120; ldll = 64; thr = 1; }
            else          { ll = (lev & 1) ? bufB : bufA; ldll = s2; thr = 0; }
            if (lev == 2)
                fwd_tiles<16>(pool, F, cur, s, ldcur, fb, ll, ldll, thr, alpha, bp, bm, ND);
            else
                fwd_tiles<8>(pool, F, cur, s, ldcur, fb, ll, ldll, thr, alpha, bp, bm, ND);
            cur = ll; ldcur = ldll; s = s2;
            bc++; grid_barrier(&g_bar, bc * (unsigned)ND);
        }
        const float* aprev = flat + 16773120;
        long lda = 64;
        for (int lev = 5; lev >= 2; lev--) {
            filt_load(F, scal + lev * 8, scal + (lev + 1) * 8, tid);
            const int s2 = 2048 >> lev;
            const float* base = flat + levoff[lev];
            float* xo = (lev & 1) ? bufB : bufA;
            long ldx = 2 * s2;
            if (lev == 2)
                bwd_tiles<32>(pool, F, base, aprev, lda, s2, xo, ldx, ND);
            else
                bwd_tiles<16>(pool, F, base, aprev, lda, s2, xo, ldx, ND);
            aprev = xo; lda = ldx;
            if (lev > 2) { bc++; grid_barrier(&g_bar, bc * (unsigned)ND); }
        }
    } else {
        const int cb = blockIdx.x - ND;
        const int nc = NB_MEGA - ND;
        // H0: lev0, vertical filter = scal + 8
        filt_load(F, scal, scal + 8, tid);
        colrecon_tiles(pool, F, flat, 2048, H0, cb, nc, 2048);
        __syncthreads();
        // H1: lev1, vertical filter = scal + 16
        filt_load(F, scal + 8, scal + 16, tid);
        colrecon_tiles(pool, F, flat + 12582912, 1024, H1, cb, nc, 512);
    }
}

// ----------------------------------------------------------------------------
// Host orchestration (graph-capturable: kernel launches only).
// ----------------------------------------------------------------------------
extern "C" void kernel_launch(void* const* d_in, const int* in_sizes, int n_in,
                              void* d_out, int out_size)
{
    const float* x    = (const float*)d_in[0];
    const float* scal = (const float*)d_in[1];
    const float* pA   = (const float*)d_in[2];
    const float* pBp  = (const float*)d_in[3];
    const float* pBm  = (const float*)d_in[4];

    float* out  = (float*)d_out;
    float* flat = out + (size_t)NSIDE * NSIDE;

    float *bufA, *bufB, *Hbuf;
    cudaGetSymbolAddress((void**)&bufA, g_bufA);
    cudaGetSymbolAddress((void**)&bufB, g_bufB);
    cudaGetSymbolAddress((void**)&Hbuf, g_H);
    float* H0 = Hbuf;
    float* H1 = Hbuf + 4096u * 2048u;

    // forward level 0: x (4096) -> flat lev0 + bufA (2048)  [resets g_bar]
    fwd2d32<<<dim3(64, 64), 256>>>(x, 4096, 4096,
                                   flat, bufA, 2048, 0,
                                   scal, scal + 8, pA, pBp, pBm);
    // forward level 1: bufA (2048) -> flat lev1 + bufB (1024)
    fwd2d32<<<dim3(32, 32), 256>>>(bufA, 2048, 2048,
                                   flat + 12582912, bufB, 1024, 0,
                                   scal + 8, scal + 16, pA, pBp, pBm);
    // mega: tail (-> bufA 1024) || H0/H1 precompute
    mega<<<NB_MEGA, 256>>>(bufA, bufB, flat, H0, H1, scal, pA, pBp, pBm);

    // backward level 1 combine: H1 + colrecon(lh1, bufA) -> bufB (2048)
    bwd_final<<<dim3(32, 32), 256>>>(flat + 12582912, bufA, 1024,
                                     H1, 1024, bufB, 2048,
                                     scal + 8, scal + 16);
    // backward level 0 combine: H0 + colrecon(lh0, bufB) -> out (4096)
    bwd_final<<<dim3(64, 64), 256>>>(flat, bufB, 2048,
                                     H0, 2048, out, 4096,
                                     scal, scal + 8);
}

// round 16
// speedup vs baseline: 1.0488x; 1.0008x over previous
#include <cuda_runtime.h>

// ----------------------------------------------------------------------------
// Despawn2D: 6-level 2D db4 circular DWT + sigmoid threshold + inverse DWT.
// fwd0, fwd1: fused tiled kernels (R8-proven; fwd0 block(0,0) resets g_bar).
// mega: blocks [0,ND) run lev2..5 fwd + 5..2 bwd tail (grid barriers);
//       blocks [ND,512) precompute H0/H1 = colrecon(hh,hl) for levels 0/1.
//       ND=368: measured crossover of tail(n) and groupC(512-n).
// bwd1, bwd0: combine kernels (H + colrecon(lh,approx) -> row recon).
// d_out layout: [ recon (4096*4096) | flat coeffs (4096*4096) ]
// flat per level: (s2, 3*s2) row-major hh|hl|lh, then approx (64*64) last.
// ----------------------------------------------------------------------------

#define NSIDE 4096
#define NB_MEGA 512
#define ND 368

__device__ float g_bufA[2048u * 2048u];
__device__ float g_bufB[2048u * 2048u];
__device__ float g_H[4096u * 2048u + 2048u * 1024u];   // H0 (32MB) + H1 (8MB)
__device__ unsigned g_bar;

__device__ __forceinline__ float2 fma2(float2 a, float2 b, float2 c)
{
    float2 d;
    asm("fma.rn.f32x2 %0, %1, %2, %3;"
        : "=l"(reinterpret_cast<unsigned long long&>(d))
        : "l"(reinterpret_cast<unsigned long long&>(a)),
          "l"(reinterpret_cast<unsigned long long&>(b)),
          "l"(reinterpret_cast<unsigned long long&>(c)));
    return d;
}

__device__ __forceinline__ float thrf(float t, float a, float bp, float bm)
{
    float s1 = 1.0f / (1.0f + __expf(-a * (t - bp)));
    float s2 = 1.0f / (1.0f + __expf( a * (t + bm)));
    return t * (s1 + s2);
}

__device__ __forceinline__ void grid_barrier(unsigned* cnt, unsigned target)
{
    __syncthreads();
    if (threadIdx.x == 0) {
        __threadfence();
        atomicAdd(cnt, 1u);
        while (*((volatile unsigned*)cnt) < target) { __nanosleep(64); }
        __threadfence();
    }
    __syncthreads();
}

struct Filt {
    float hH[8], wH[8], hV[8], wV[8];
    float2 hH2[8], wH2[8], hV2[8], wV2[8];
    float2 cxe[4], cxo[4];
    float2 cve[4], cvo[4];
};

__device__ __forceinline__ void filt_load(Filt& F, const float* hHp, const float* hVp, int tid)
{
    if (tid < 8) { F.hH[tid] = hHp[tid]; F.hV[tid] = hVp[tid]; }
    __syncthreads();
    if (tid < 8) {
        float s = (tid & 1) ? -1.0f : 1.0f;
        float wh = F.hH[7 - tid] * s;
        float wv = F.hV[7 - tid] * s;
        F.wH[tid] = wh;           F.wV[tid] = wv;
        F.hH2[tid] = make_float2(F.hH[tid], F.hH[tid]);
        F.wH2[tid] = make_float2(wh, wh);
        F.hV2[tid] = make_float2(F.hV[tid], F.hV[tid]);
        F.wV2[tid] = make_float2(wv, wv);
    }
    __syncthreads();
    if (tid < 4) {
        F.cxe[tid] = make_float2(F.wH[2 * tid],     F.hH[2 * tid]);
        F.cxo[tid] = make_float2(F.wH[2 * tid + 1], F.hH[2 * tid + 1]);
        F.cve[tid] = make_float2(F.wV[2 * tid],     F.hV[2 * tid]);
        F.cvo[tid] = make_float2(F.wV[2 * tid + 1], F.hV[2 * tid + 1]);
    }
    __syncthreads();
}

// ----------------------------------------------------------------------------
// Big fused forward (TI=32). R8-proven scalar high-MLP loads.
// Block (0,0) resets g_bar (graph-safe: stream-ordered before mega).
// ----------------------------------------------------------------------------
__global__ __launch_bounds__(256)
void fwd2d32(const float* __restrict__ X, int s, long ldx,
             float* __restrict__ flatb,
             float* __restrict__ LL, long ldll, int thrLL,
             const float* __restrict__ hHp, const float* __restrict__ hVp,
             const float* __restrict__ pA, const float* __restrict__ pBp,
             const float* __restrict__ pBm)
{
    __shared__ __align__(16) float4 sx4[70][19];
    __shared__ __align__(16) float2 sda[70][34];
    __shared__ Filt F;
    const int tid = threadIdx.x;
    const int wid = tid >> 5, lane = tid & 31;
    if (tid == 0 && blockIdx.x == 0 && blockIdx.y == 0) g_bar = 0;
    filt_load(F, hHp, hVp, tid);

    const int s2 = s >> 1;
    const int i0 = blockIdx.y << 5, j0 = blockIdx.x << 5;
    const int mask = s - 1;
    const int rb = 2 * i0 - 7, cb = 2 * j0 - 7;

#pragma unroll
    for (int k = 0; k < 9; k++) {
        const int rr = wid + 8 * k;
        if (rr < 70) {
            const float* xr = X + (long)((rb + rr) & mask) * ldx;
            float* dst = (float*)(&sx4[rr][0]);
#pragma unroll
            for (int cc = 0; cc < 3; cc++) {
                const int c = lane + 32 * cc;
                if (c < 70) dst[c] = xr[(cb + c) & mask];
            }
        }
    }
    __syncthreads();

#pragma unroll
    for (int k = 0; k < 5; k++) {
        const int t = tid + 256 * k;
        if (t < 70 * 16) {
            const int rr = t >> 4, jp = t & 15;
            float4 q0 = sx4[rr][jp], q1 = sx4[rr][jp + 1], q2 = sx4[rr][jp + 2];
            float xx[12] = {q0.x, q0.y, q0.z, q0.w, q1.x, q1.y, q1.z, q1.w,
                            q2.x, q2.y, q2.z, q2.w};
            float2 dd = make_float2(0.f, 0.f), aa = make_float2(0.f, 0.f);
#pragma unroll
            for (int m = 0; m < 8; m++) {
                float2 p = make_float2(xx[m], xx[m + 2]);
                dd = fma2(F.wH2[7 - m], p, dd);
                aa = fma2(F.hH2[7 - m], p, aa);
            }
            *(float4*)&sda[rr][2 * jp] = make_float4(dd.x, aa.x, dd.y, aa.y);
        }
    }
    __syncthreads();

    const float alpha = *pA, bp = *pBp, bm = *pBm;
    const int tx = lane, ty = wid;
    const int j = j0 + tx;
    const long ldflat = 3L * s2;
    float2 v[14];
#pragma unroll
    for (int m = 0; m < 14; m++) v[m] = sda[8 * ty + m][tx];
#pragma unroll
    for (int k = 0; k < 4; k++) {
        float2 e1 = make_float2(0.f, 0.f), e2 = make_float2(0.f, 0.f);
#pragma unroll
        for (int m = 0; m < 8; m++) {
            float2 da = v[2 * k + m];
            e1 = fma2(F.wV2[7 - m], da, e1);
            e2 = fma2(F.hV2[7 - m], da, e2);
        }
        const int i = i0 + 4 * ty + k;
        const long ro = (long)i * ldflat;
        flatb[ro + j]          = thrf(e1.x, alpha, bp, bm);
        flatb[ro + s2 + j]     = thrf(e2.x, alpha, bp, bm);
        flatb[ro + 2 * s2 + j] = thrf(e1.y, alpha, bp, bm);
        LL[(long)i * ldll + j] = thrLL ? thrf(e2.y, alpha, bp, bm) : e2.y;
    }
}

// ----------------------------------------------------------------------------
// bwd combine kernel: X = rowrecon( H (precomputed), colrecon(lh, ap) ).
// ----------------------------------------------------------------------------
__global__ __launch_bounds__(256)
void bwd_final(const float* __restrict__ base,
               const float* __restrict__ ap, long lda,
               const float* __restrict__ Hb,
               int s2,
               float* __restrict__ X, long ldx,
               const float* __restrict__ hHp, const float* __restrict__ hVp)
{
    __shared__ float2 scl[36][37];
    __shared__ float2 sh2[64][37];
    __shared__ Filt F;
    const int tid = threadIdx.x;
    const int wid = tid >> 5, lane = tid & 31;
    filt_load(F, hHp, hVp, tid);

    const int i0 = blockIdx.y << 6, j0 = blockIdx.x << 6;
    const int mask = s2 - 1;
    const long ldc = 3L * s2;
    const int rbb = i0 >> 1, cbb = j0 >> 1;

#pragma unroll
    for (int k = 0; k < 6; k++) {
        const int t = tid + 256 * k;
        if (t < 36 * 36) {
            const int rr = t / 36, cc = t - rr * 36;
            const int gr = (rbb + rr) & mask, gc = (cbb + cc) & mask;
            scl[rr][cc] = make_float2(base[(long)gr * ldc + 2 * s2 + gc],
                                      ap[(long)gr * lda + gc]);
        }
    }
#pragma unroll
    for (int k = 0; k < 9; k++) {
        const int t = tid + 256 * k;
        if (t < 64 * 36) {
            const int r = t / 36, cc = t - r * 36;
            sh2[r][cc].x = Hb[(long)(i0 + r) * s2 + ((cbb + cc) & mask)];
        }
    }
    __syncthreads();

#pragma unroll
    for (int k = 0; k < 5; k++) {
        const int t = tid + 256 * k;
        if (t < 32 * 36) {
            const int m = t / 36, cc = t - m * 36;
            float2 c0 = scl[m][cc], c1 = scl[m + 1][cc], c2 = scl[m + 2][cc],
                   c3 = scl[m + 3][cc], c4 = scl[m + 4][cc];
            float2 he = make_float2(0.f, 0.f), ho = make_float2(0.f, 0.f);
            he = fma2(F.cve[0], c0, he); he = fma2(F.cve[1], c1, he);
            he = fma2(F.cve[2], c2, he); he = fma2(F.cve[3], c3, he);
            ho = fma2(F.cvo[0], c1, ho); ho = fma2(F.cvo[1], c2, ho);
            ho = fma2(F.cvo[2], c3, ho); ho = fma2(F.cvo[3], c4, ho);
            sh2[2 * m][cc].y     = he.x + he.y;
            sh2[2 * m + 1][cc].y = ho.x + ho.y;
        }
    }
    __syncthreads();

#pragma unroll
    for (int k = 0; k < 8; k++) {
        const int r = wid + 8 * k;
        float2 q0 = sh2[r][lane], q1 = sh2[r][lane + 1], q2 = sh2[r][lane + 2],
               q3 = sh2[r][lane + 3], q4 = sh2[r][lane + 4];
        float2 ae = make_float2(0.f, 0.f), ao = make_float2(0.f, 0.f);
        ae = fma2(F.cxe[0], q0, ae); ae = fma2(F.cxe[1], q1, ae);
        ae = fma2(F.cxe[2], q2, ae); ae = fma2(F.cxe[3], q3, ae);
        ao = fma2(F.cxo[0], q1, ao); ao = fma2(F.cxo[1], q2, ao);
        ao = fma2(F.cxo[2], q3, ao); ao = fma2(F.cxo[3], q4, ao);
        float2 v;
        v.x = ae.x + ae.y;
        v.y = ao.x + ao.y;
        *(float2*)&X[(long)(i0 + r) * ldx + (j0 + 2 * lane)] = v;
    }
}

// ----------------------------------------------------------------------------
// Group C: H = colrecon(hh, hl) tiles over [start : stride : end).
// ----------------------------------------------------------------------------
__device__ void colrecon_tiles(float* pool, const Filt& F,
                               const float* __restrict__ base, int s2,
                               float* __restrict__ H,
                               int start, int stride, int endT)
{
    float2 (*sc1)[33] = reinterpret_cast<float2(*)[33]>(pool);
    float2 (*sc2)[33] = reinterpret_cast<float2(*)[33]>(pool + 36 * 33 * 2);
    const int tid = threadIdx.x;
    const int mask = s2 - 1;
    const long ldc = 3L * s2;
    const int ntj = s2 / 64;

    for (int t = start; t < endT; t += stride) {
        const int by = t / ntj, bx = t - by * ntj;
        const int i0 = by * 64, j0 = bx * 64;
        const int rbb = i0 >> 1;
#pragma unroll
        for (int k = 0; k < 5; k++) {
            const int idx = tid + 256 * k;
            if (idx < 36 * 32) {
                const int rr = idx >> 5, c2 = idx & 31;
                const int gr = (rbb + rr) & mask;
                const long o = (long)gr * ldc + j0 + 2 * c2;
                sc1[rr][c2] = *(const float2*)&base[o];
                sc2[rr][c2] = *(const float2*)&base[o + s2];
            }
        }
        __syncthreads();
#pragma unroll
        for (int k = 0; k < 4; k++) {
            const int idx = tid + 256 * k;
            if (idx < 32 * 32) {
                const int m = idx >> 5, c2 = idx & 31;
                float2 c1v[5], c2v[5];
#pragma unroll
                for (int u = 0; u < 5; u++) { c1v[u] = sc1[m + u][c2]; c2v[u] = sc2[m + u][c2]; }
                float2 he = make_float2(0.f, 0.f), ho = make_float2(0.f, 0.f);
#pragma unroll
                for (int u = 0; u < 4; u++) {
                    he = fma2(F.wV2[2 * u],     c1v[u],     he);
                    he = fma2(F.hV2[2 * u],     c2v[u],     he);
                    ho = fma2(F.wV2[2 * u + 1], c1v[u + 1], ho);
                    ho = fma2(F.hV2[2 * u + 1], c2v[u + 1], ho);
                }
                *(float2*)&H[(long)(i0 + 2 * m)     * s2 + j0 + 2 * c2] = he;
                *(float2*)&H[(long)(i0 + 2 * m + 1) * s2 + j0 + 2 * c2] = ho;
            }
        }
        __syncthreads();
    }
}

// ----------------------------------------------------------------------------
// Tail device functions (R8).
// ----------------------------------------------------------------------------
template<int TI>
__device__ void fwd_tiles(float* pool, const Filt& F,
                          const float* __restrict__ X, int s, long ldx,
                          float* __restrict__ flatb,
                          float* __restrict__ LL, long ldll, int thrLL,
                          float alpha, float bp, float bm, int nb)
{
    constexpr int NW = 2 * TI + 6;
    constexpr int C4 = NW / 4 + 2;
    float4 (*sx4)[C4] = reinterpret_cast<float4(*)[C4]>(pool);
    float2 (*sda)[TI + 2] = reinterpret_cast<float2(*)[TI + 2]>(pool + NW * C4 * 4);
    const int s2 = s >> 1;
    const int nt = s2 / TI;
    const int mask = s - 1;
    const int tid = threadIdx.x;
    const long ldflat = 3L * s2;
    constexpr int TIH = TI / 2;
    constexpr int NL1 = (NW * NW + 255) / 256;
    constexpr int NL2 = (NW * TIH + 255) / 256;
    constexpr int NL3 = (TI * TI + 255) / 256;

    for (int tile = blockIdx.x; tile < nt * nt; tile += nb) {
        const int by = tile / nt, bx = tile - by * nt;
        const int i0 = by * TI, j0 = bx * TI;
        const int rb = 2 * i0 - 7, cb = 2 * j0 - 7;
#pragma unroll
        for (int k = 0; k < NL1; k++) {
            const int t = tid + 256 * k;
            if (t < NW * NW) {
                const int rr = t / NW, cc = t - rr * NW;
                ((float*)(&sx4[rr][0]))[cc] =
                    X[(long)((rb + rr) & mask) * ldx + ((cb + cc) & mask)];
            }
        }
        __syncthreads();
#pragma unroll
        for (int k = 0; k < NL2; k++) {
            const int t = tid + 256 * k;
            if (t < NW * TIH) {
                const int rr = t / TIH, jp = t - rr * TIH;
                float4 q0 = sx4[rr][jp], q1 = sx4[rr][jp + 1], q2 = sx4[rr][jp + 2];
                float xx[12] = {q0.x, q0.y, q0.z, q0.w, q1.x, q1.y, q1.z, q1.w,
                                q2.x, q2.y, q2.z, q2.w};
                float2 dd = make_float2(0.f, 0.f), aa = make_float2(0.f, 0.f);
#pragma unroll
                for (int m = 0; m < 8; m++) {
                    float2 p = make_float2(xx[m], xx[m + 2]);
                    dd = fma2(F.wH2[7 - m], p, dd);
                    aa = fma2(F.hH2[7 - m], p, aa);
                }
                *(float4*)&sda[rr][2 * jp] = make_float4(dd.x, aa.x, dd.y, aa.y);
            }
        }
        __syncthreads();
#pragma unroll
        for (int k = 0; k < NL3; k++) {
            const int t = tid + 256 * k;
            if (t < TI * TI) {
                const int tx = t % TI, il = t / TI;
                const int i = i0 + il, j = j0 + tx;
                float2 e1 = make_float2(0.f, 0.f), e2 = make_float2(0.f, 0.f);
#pragma unroll
                for (int m = 0; m < 8; m++) {
                    float2 da = sda[2 * il + m][tx];
                    e1 = fma2(F.wV2[7 - m], da, e1);
                    e2 = fma2(F.hV2[7 - m], da, e2);
                }
                const long ro = (long)i * ldflat;
                flatb[ro + j]          = thrf(e1.x, alpha, bp, bm);
                flatb[ro + s2 + j]     = thrf(e2.x, alpha, bp, bm);
                flatb[ro + 2 * s2 + j] = thrf(e1.y, alpha, bp, bm);
                LL[(long)i * ldll + j] = thrLL ? thrf(e2.y, alpha, bp, bm) : e2.y;
            }
        }
        __syncthreads();
    }
}

template<int TO>
__device__ void bwd_tiles(float* pool, const Filt& F,
                          const float* __restrict__ base,
                          const float* __restrict__ ap, long lda,
                          int s2, float* __restrict__ X, long ldx, int nb)
{
    constexpr int NC = TO / 2 + 4;
    constexpr int LDC = NC + 1;
    float2 (*sc1)[LDC] = reinterpret_cast<float2(*)[LDC]>(pool);
    float2 (*sc2)[LDC] = reinterpret_cast<float2(*)[LDC]>(pool + 2 * NC * LDC);
    float2 (*sh2)[LDC] = reinterpret_cast<float2(*)[LDC]>(pool + 4 * NC * LDC);
    const int nt = (2 * s2) / TO;
    const int mask = s2 - 1;
    const long ldc = 3L * s2;
    const int tid = threadIdx.x;
    constexpr int NL1 = (NC * NC + 255) / 256;
    constexpr int NL2 = ((TO / 2) * NC + 255) / 256;
    constexpr int NL3 = (TO * (TO / 2) + 255) / 256;

    for (int tile = blockIdx.x; tile < nt * nt; tile += nb) {
        const int by = tile / nt, bx = tile - by * nt;
        const int i0 = by * TO, j0 = bx * TO;
        const int rbb = i0 >> 1, cbb = j0 >> 1;
#pragma unroll
        for (int k = 0; k < NL1; k++) {
            const int t = tid + 256 * k;
            if (t < NC * NC) {
                const int rr = t / NC, cc = t - rr * NC;
                const int gr = (rbb + rr) & mask, gc = (cbb + cc) & mask;
                const long o = (long)gr * ldc + gc;
                sc1[rr][cc] = make_float2(base[o],      base[o + 2 * s2]);
                sc2[rr][cc] = make_float2(base[o + s2], ap[(long)gr * lda + gc]);
            }
        }
        __syncthreads();
#pragma unroll
        for (int k = 0; k < NL2; k++) {
            const int t = tid + 256 * k;
            if (t < (TO / 2) * NC) {
                const int m = t / NC, cc = t - m * NC;
                float2 c1[5], c2[5];
#pragma unroll
                for (int u = 0; u < 5; u++) { c1[u] = sc1[m + u][cc]; c2[u] = sc2[m + u][cc]; }
                float2 he = make_float2(0.f, 0.f), ho = make_float2(0.f, 0.f);
#pragma unroll
                for (int u = 0; u < 4; u++) {
                    he = fma2(F.wV2[2 * u],     c1[u],     he);
                    he = fma2(F.hV2[2 * u],     c2[u],     he);
                    ho = fma2(F.wV2[2 * u + 1], c1[u + 1], ho);
                    ho = fma2(F.hV2[2 * u + 1], c2[u + 1], ho);
                }
                sh2[2 * m][cc]     = he;
                sh2[2 * m + 1][cc] = ho;
            }
        }
        __syncthreads();
#pragma unroll
        for (int k = 0; k < NL3; k++) {
            const int t = tid + 256 * k;
            if (t < TO * (TO / 2)) {
                const int c2 = t % (TO / 2), r = t / (TO / 2);
                float2 q0 = sh2[r][c2], q1 = sh2[r][c2 + 1], q2 = sh2[r][c2 + 2],
                       q3 = sh2[r][c2 + 3], q4 = sh2[r][c2 + 4];
                float2 ae = make_float2(0.f, 0.f), ao = make_float2(0.f, 0.f);
                ae = fma2(F.cxe[0], q0, ae); ae = fma2(F.cxe[1], q1, ae);
                ae = fma2(F.cxe[2], q2, ae); ae = fma2(F.cxe[3], q3, ae);
                ao = fma2(F.cxo[0], q1, ao); ao = fma2(F.cxo[1], q2, ao);
                ao = fma2(F.cxo[2], q3, ao); ao = fma2(F.cxo[3], q4, ao);
                float2 v;
                v.x = ae.x + ae.y;
                v.y = ao.x + ao.y;
                *(float2*)&X[(long)(i0 + r) * ldx + (j0 + 2 * c2)] = v;
            }
        }
        __syncthreads();
    }
}

// ----------------------------------------------------------------------------
// MEGA kernel: group D (blocks [0,ND)) = tail; group C = H0 + H1 precompute.
// ----------------------------------------------------------------------------
__global__ __launch_bounds__(256, 4)
void mega(float* bufA, float* bufB, float* flat, float* H0, float* H1,
          const float* __restrict__ scal,
          const float* pA, const float* pBp, const float* pBm)
{
    __shared__ __align__(16) float pool[4864];
    __shared__ Filt F;
    const int tid = threadIdx.x;
    const size_t levoff[6] = {0, 12582912, 15728640, 16515072, 16711680, 16760832};

    if (blockIdx.x < ND) {
        const float alpha = *pA, bp = *pBp, bm = *pBm;
        unsigned bc = 0;
        const float* cur = bufB;
        long ldcur = 1024;
        int s = 1024;
        for (int lev = 2; lev <= 5; lev++) {
            filt_load(F, scal + lev * 8, scal + (lev + 1) * 8, tid);
            const int s2 = s >> 1;
            float* fb = flat + levoff[lev];
            float* ll; long ldll; int thr;
            if (lev == 5) { ll = flat + 16773120; ldll = 64; thr = 1; }
            else          { ll = (lev & 1) ? bufB : bufA; ldll = s2; thr = 0; }
            if (lev == 2)
                fwd_tiles<16>(pool, F, cur, s, ldcur, fb, ll, ldll, thr, alpha, bp, bm, ND);
            else
                fwd_tiles<8>(pool, F, cur, s, ldcur, fb, ll, ldll, thr, alpha, bp, bm, ND);
            cur = ll; ldcur = ldll; s = s2;
            bc++; grid_barrier(&g_bar, bc * (unsigned)ND);
        }
        const float* aprev = flat + 16773120;
        long lda = 64;
        for (int lev = 5; lev >= 2; lev--) {
            filt_load(F, scal + lev * 8, scal + (lev + 1) * 8, tid);
            const int s2 = 2048 >> lev;
            const float* base = flat + levoff[lev];
            float* xo = (lev & 1) ? bufB : bufA;
            long ldx = 2 * s2;
            if (lev == 2)
                bwd_tiles<32>(pool, F, base, aprev, lda, s2, xo, ldx, ND);
            else
                bwd_tiles<16>(pool, F, base, aprev, lda, s2, xo, ldx, ND);
            aprev = xo; lda = ldx;
            if (lev > 2) { bc++; grid_barrier(&g_bar, bc * (unsigned)ND); }
        }
    } else {
        const int cb = blockIdx.x - ND;
        const int nc = NB_MEGA - ND;
        // H0: lev0, vertical filter = scal + 8
        filt_load(F, scal, scal + 8, tid);
        colrecon_tiles(pool, F, flat, 2048, H0, cb, nc, 2048);
        __syncthreads();
        // H1: lev1, vertical filter = scal + 16
        filt_load(F, scal + 8, scal + 16, tid);
        colrecon_tiles(pool, F, flat + 12582912, 1024, H1, cb, nc, 512);
    }
}

// ----------------------------------------------------------------------------
// Host orchestration (graph-capturable: kernel launches only).
// ----------------------------------------------------------------------------
extern "C" void kernel_launch(void* const* d_in, const int* in_sizes, int n_in,
                              void* d_out, int out_size)
{
    const float* x    = (const float*)d_in[0];
    const float* scal = (const float*)d_in[1];
    const float* pA   = (const float*)d_in[2];
    const float* pBp  = (const float*)d_in[3];
    const float* pBm  = (const float*)d_in[4];

    float* out  = (float*)d_out;
    float* flat = out + (size_t)NSIDE * NSIDE;

    float *bufA, *bufB, *Hbuf;
    cudaGetSymbolAddress((void**)&bufA, g_bufA);
    cudaGetSymbolAddress((void**)&bufB, g_bufB);
    cudaGetSymbolAddress((void**)&Hbuf, g_H);
    float* H0 = Hbuf;
    float* H1 = Hbuf + 4096u * 2048u;

    // forward level 0: x (4096) -> flat lev0 + bufA (2048)  [resets g_bar]
    fwd2d32<<<dim3(64, 64), 256>>>(x, 4096, 4096,
                                   flat, bufA, 2048, 0,
                                   scal, scal + 8, pA, pBp, pBm);
    // forward level 1: bufA (2048) -> flat lev1 + bufB (1024)
    fwd2d32<<<dim3(32, 32), 256>>>(bufA, 2048, 2048,
                                   flat + 12582912, bufB, 1024, 0,
                                   scal + 8, scal + 16, pA, pBp, pBm);
    // mega: tail (-> bufA 1024) || H0/H1 precompute
    mega<<<NB_MEGA, 256>>>(bufA, bufB, flat, H0, H1, scal, pA, pBp, pBm);

    // backward level 1 combine: H1 + colrecon(lh1, bufA) -> bufB (2048)
    bwd_final<<<dim3(32, 32), 256>>>(flat + 12582912, bufA, 1024,
                                     H1, 1024, bufB, 2048,
                                     scal + 8, scal + 16);
    // backward level 0 combine: H0 + colrecon(lh0, bufB) -> out (4096)
    bwd_final<<<dim3(64, 64), 256>>>(flat, bufB, 2048,
                                     H0, 2048, out, 4096,
                                     scal, scal + 8);
}